// round 9
// baseline (speedup 1.0000x reference)
#include <cuda_runtime.h>
#include <math.h>
#include <cstdint>

// Problem dims
#define B_SZ 512
#define T_IN 1125
#define E_SZ 5
#define C_SZ 40
#define L_SZ 216
#define G_SZ 40
#define H_SZ 10
#define KK   125

// ---- persistent scratch ----
__device__ __align__(16) float d_Wcomb[KK*G_SZ];        // [kk][g]
__device__ __align__(16) float d_bg[G_SZ];
__device__ __align__(16) float d_xg[B_SZ*L_SZ*G_SZ];    // [b][t][g]

__device__ __forceinline__ float tanh_a(float x) {
    float r; asm("tanh.approx.f32 %0, %1;" : "=f"(r) : "f"(x)); return r;
}
__device__ __forceinline__ uint32_t smem_u32(const void* p) {
    uint32_t a;
    asm("{ .reg .u64 t; cvta.to.shared.u64 t, %1; cvt.u32.u64 %0, t; }" : "=r"(a) : "l"(p));
    return a;
}

// ============================================================
// Kernel 0: weight fold (R6-proven). 40 CTAs, one gate each.
// ============================================================
__global__ void __launch_bounds__(256) prep_kernel(
        const float* __restrict__ wt,     // [40][25]
        const float* __restrict__ tb,     // [40]
        const float* __restrict__ ws,     // [40][40][5]
        const float* __restrict__ gamma,
        const float* __restrict__ beta,
        const float* __restrict__ mean,
        const float* __restrict__ var,
        const float* __restrict__ wih,    // [40][40]
        const float* __restrict__ bih,
        const float* __restrict__ bhh)
{
    __shared__ __align__(16) float s_ws[C_SZ*C_SZ*E_SZ];   // 8000
    __shared__ __align__(16) float s_wt[C_SZ*25];
    __shared__ float s_wr[C_SZ], s_wsc[C_SZ], s_shift[C_SZ], s_tb[C_SZ];
    __shared__ float A_s[C_SZ*E_SZ];
    __shared__ float red[8];
    int t = threadIdx.x;
    int g = blockIdx.x;

    for (int i = t; i < 2000; i += 256) ((float4*)s_ws)[i] = ((const float4*)ws)[i];
    for (int i = t; i < 250;  i += 256) ((float4*)s_wt)[i] = ((const float4*)wt)[i];
    if (t < C_SZ) {
        float sc = gamma[t] * rsqrtf(var[t] + 1e-5f);
        float wr = wih[g*C_SZ + t];
        s_wr[t]  = wr;
        s_wsc[t] = wr * sc;
        s_shift[t] = beta[t] - mean[t]*sc;
        s_tb[t] = tb[t];
    }
    __syncthreads();

    if (t < C_SZ*E_SZ) {
        int cp = t / E_SZ, e = t % E_SZ;
        float s = 0.f;
        #pragma unroll 8
        for (int c = 0; c < C_SZ; c++) s += s_wsc[c] * s_ws[c*200 + cp*E_SZ + e];
        A_s[t] = s;
    }
    __syncthreads();

    if (t < KK) {
        int k = t / E_SZ, e = t % E_SZ;
        float s = 0.f;
        #pragma unroll 8
        for (int cp = 0; cp < C_SZ; cp++) s += A_s[cp*E_SZ + e] * s_wt[cp*25 + k];
        d_Wcomb[t*G_SZ + g] = s * (1.0f/25.0f);
    }

    float part = 0.f;
    for (int idx = t; idx < 1600; idx += 256) {
        int c = idx / C_SZ, cp = idx % C_SZ;
        const float* w5 = &s_ws[c*200 + cp*E_SZ];
        float s5 = w5[0]+w5[1]+w5[2]+w5[3]+w5[4];
        part += s_wsc[c] * s_tb[cp] * s5;
    }
    if (t < C_SZ) part += s_wr[t] * s_shift[t];
    #pragma unroll
    for (int o = 16; o > 0; o >>= 1) part += __shfl_xor_sync(0xffffffffu, part, o);
    if ((t & 31) == 0) red[t >> 5] = part;
    __syncthreads();
    if (t == 0) {
        float s = red[0]+red[1]+red[2]+red[3]+red[4]+red[5]+red[6]+red[7];
        d_bg[g] = bih[g] + bhh[g] + s;
    }
}

// ============================================================
// Kernel 1: conv/pool/GEMM. 4g x 8p register tile (FMA-bound),
// weights staged up-front (overlapped with x load), direct-
// transposed box sums. 96 threads, 64.3 KB smem, 3 CTAs/SM.
// ============================================================
#define CONV_THREADS 96
#define PTILE 72
// smem floats (no aliasing)
#define OFF_WS   0                 // 5000
#define OFF_BG   5000              // 40
#define OFF_XS   5040              // 2024 (2020 used)
#define OFF_BST  7064              // 9000 = 125*72
#define CONV_SMEM_FLOATS (7064 + 9000)          // 16064
#define CONV_SMEM_BYTES  (CONV_SMEM_FLOATS*4)   // 64256

__global__ void __launch_bounds__(CONV_THREADS) conv_kernel(const float* __restrict__ x)
{
    extern __shared__ float sm[];
    float* Ws   = sm + OFF_WS;
    float* bg_s = sm + OFF_BG;
    float* xs   = sm + OFF_XS;
    float* Bst  = sm + OFF_BST;

    int tid = threadIdx.x;
    int q   = blockIdx.x;              // tile 0..2
    int b   = blockIdx.y;

    // overlap: weights + bias + x slab all issued together
    const float* xb = x + (size_t)b*(T_IN*E_SZ) + q*(PTILE*5*E_SZ);   // q*1800
    for (int i = tid; i < 2020; i += CONV_THREADS) xs[i] = xb[i];
    for (int i = tid; i < KK*G_SZ; i += CONV_THREADS) Ws[i] = d_Wcomb[i];
    if (tid < G_SZ) bg_s[tid] = d_bg[tid];
    __syncthreads();

    // box sums written directly transposed:
    // for t in [0,380): s = sum_{j<25} xs[(t+j)*5+e]
    //   Bst[(5*(t%5) + 25*i + e)*72 + (t/5 - i)] = s for i=0..4, pl in range
    {
        int e = tid % 5, seg = tid / 5;      // seg 0..18 (tid 95 idle)
        int t0 = seg*20;
        if (t0 < 380) {
            float s = 0.f;
            #pragma unroll
            for (int j = 0; j < 25; j++) s += xs[(t0+j)*5 + e];
            #pragma unroll 2
            for (int tt = t0; tt < t0+20; tt++) {
                if (tt > t0) s += xs[(tt+24)*5+e] - xs[(tt-1)*5+e];
                int qd = tt / 5, k0 = tt - 5*qd;
                int base = (5*k0 + e)*PTILE + qd;
                #pragma unroll
                for (int i = 0; i < 5; i++) {
                    int pl = qd - i;
                    if (pl >= 0 && pl < PTILE)
                        Bst[base + i*(25*PTILE) - i] = s;
                }
            }
        }
    }
    __syncthreads();

    if (tid < 90) {
        int gq = tid / 9;             // 0..9  -> gates 4gq..4gq+3
        int pq = tid - gq*9;          // 0..8  -> p 8pq..8pq+7
        const float4* wp = (const float4*)Ws  + gq;       // wp[kk*10]
        const float4* xq = (const float4*)Bst + 2*pq;     // xq[kk*18], xq[kk*18+1]

        float4 bg4 = ((const float4*)bg_s)[gq];
        float a0[8], a1[8], a2[8], a3[8];
        #pragma unroll
        for (int j = 0; j < 8; j++) { a0[j]=bg4.x; a1[j]=bg4.y; a2[j]=bg4.z; a3[j]=bg4.w; }

        #pragma unroll 5
        for (int kk = 0; kk < KK; kk++) {
            float4 w   = wp[kk*10];
            float4 xv0 = xq[kk*18];
            float4 xv1 = xq[kk*18 + 1];
            a0[0]=fmaf(w.x,xv0.x,a0[0]); a0[1]=fmaf(w.x,xv0.y,a0[1]);
            a0[2]=fmaf(w.x,xv0.z,a0[2]); a0[3]=fmaf(w.x,xv0.w,a0[3]);
            a0[4]=fmaf(w.x,xv1.x,a0[4]); a0[5]=fmaf(w.x,xv1.y,a0[5]);
            a0[6]=fmaf(w.x,xv1.z,a0[6]); a0[7]=fmaf(w.x,xv1.w,a0[7]);
            a1[0]=fmaf(w.y,xv0.x,a1[0]); a1[1]=fmaf(w.y,xv0.y,a1[1]);
            a1[2]=fmaf(w.y,xv0.z,a1[2]); a1[3]=fmaf(w.y,xv0.w,a1[3]);
            a1[4]=fmaf(w.y,xv1.x,a1[4]); a1[5]=fmaf(w.y,xv1.y,a1[5]);
            a1[6]=fmaf(w.y,xv1.z,a1[6]); a1[7]=fmaf(w.y,xv1.w,a1[7]);
            a2[0]=fmaf(w.z,xv0.x,a2[0]); a2[1]=fmaf(w.z,xv0.y,a2[1]);
            a2[2]=fmaf(w.z,xv0.z,a2[2]); a2[3]=fmaf(w.z,xv0.w,a2[3]);
            a2[4]=fmaf(w.z,xv1.x,a2[4]); a2[5]=fmaf(w.z,xv1.y,a2[5]);
            a2[6]=fmaf(w.z,xv1.z,a2[6]); a2[7]=fmaf(w.z,xv1.w,a2[7]);
            a3[0]=fmaf(w.w,xv0.x,a3[0]); a3[1]=fmaf(w.w,xv0.y,a3[1]);
            a3[2]=fmaf(w.w,xv0.z,a3[2]); a3[3]=fmaf(w.w,xv0.w,a3[3]);
            a3[4]=fmaf(w.w,xv1.x,a3[4]); a3[5]=fmaf(w.w,xv1.y,a3[5]);
            a3[6]=fmaf(w.w,xv1.z,a3[6]); a3[7]=fmaf(w.w,xv1.w,a3[7]);
        }

        // xg layout [b][t][g]
        int p0 = q*PTILE + 8*pq;
        float* dst = d_xg + (size_t)b*(L_SZ*G_SZ) + p0*G_SZ + 4*gq;
        #pragma unroll
        for (int j = 0; j < 8; j++)
            *(float4*)(dst + j*G_SZ) = make_float4(a0[j], a1[j], a2[j], a3[j]);
    }
}

// ============================================================
// Kernel 2: LSTM scan + FC. 2 batches per warp (ILP), contiguous
// xg slices staged via cp.async. (R8 verbatim)
// ============================================================
#define LSTM_WARPS 2
#define BPW 2
#define XSLICE_FLOATS (L_SZ*G_SZ)            // 8640
#define XSLICE_BYTES  (XSLICE_FLOATS*4)      // 34560
#define LSTM_SMEM_BYTES (LSTM_WARPS*BPW*XSLICE_BYTES + 256)

__global__ void __launch_bounds__(32*LSTM_WARPS) lstm_kernel(
        const float* __restrict__ whh,  // [40][10]
        const float* __restrict__ fcw,  // [2][10]
        const float* __restrict__ fcb,
        float* __restrict__ out)
{
    extern __shared__ float xsm[];
    int warp = threadIdx.x >> 5;
    int lid  = threadIdx.x & 31;
    int b0   = blockIdx.x*(LSTM_WARPS*BPW) + warp*BPW;

    {
        uint32_t dst0 = smem_u32(xsm) + warp*BPW*XSLICE_BYTES;
        #pragma unroll
        for (int u = 0; u < BPW; u++) {
            const char* src0 = (const char*)(d_xg + (size_t)(b0+u)*XSLICE_FLOATS);
            uint32_t d0 = dst0 + u*XSLICE_BYTES;
            for (int c = lid; c < 2160; c += 32) {
                asm volatile("cp.async.ca.shared.global [%0], [%1], 16;"
                             :: "r"(d0 + (uint32_t)(c*16)), "l"(src0 + (size_t)c*16));
            }
        }
        asm volatile("cp.async.commit_group;" ::: "memory");
        asm volatile("cp.async.wait_group 0;" ::: "memory");
        __syncwarp();
    }
    const float* xw[BPW];
    xw[0] = xsm + warp*BPW*XSLICE_FLOATS;
    xw[1] = xw[0] + XSLICE_FLOATS;

    int r = min(lid, 19);
    float wa[H_SZ], wb[H_SZ];
    #pragma unroll
    for (int j = 0; j < H_SZ; j++) {
        wa[j] = whh[r*H_SZ + j];
        wb[j] = whh[(r+20)*H_SZ + j];
    }
    const float sc2 = (lid < 10) ? 1.0f : 0.5f;
    const float k1  = (lid < 10) ? 1.0f : 0.5f;
    const float k0  = (lid < 10) ? 0.0f : 0.5f;

    float h[BPW][H_SZ], cc[BPW], cur1[BPW], cur2[BPW];
    #pragma unroll
    for (int u = 0; u < BPW; u++) {
        #pragma unroll
        for (int j = 0; j < H_SZ; j++) h[u][j] = 0.f;
        cc[u] = 0.f;
        cur1[u] = xw[u][r];
        cur2[u] = xw[u][20 + r];
    }

    for (int t = 0; t < L_SZ; t++) {
        float n1[BPW], n2[BPW];
        #pragma unroll
        for (int u = 0; u < BPW; u++) {           // overrun at t=215 lands in pad
            n1[u] = xw[u][(t+1)*G_SZ + r];
            n2[u] = xw[u][(t+1)*G_SZ + 20 + r];
        }
        float a1[BPW], a2[BPW];
        #pragma unroll
        for (int u = 0; u < BPW; u++) {
            float s1a = cur1[u], s1b = 0.f, s2a = cur2[u], s2b = 0.f;
            #pragma unroll
            for (int j = 0; j < 5; j++) {
                s1a = fmaf(wa[j],   h[u][j],   s1a);
                s1b = fmaf(wa[j+5], h[u][j+5], s1b);
                s2a = fmaf(wb[j],   h[u][j],   s2a);
                s2b = fmaf(wb[j+5], h[u][j+5], s2b);
            }
            float g1 = s1a + s1b;
            float g2 = s2a + s2b;
            a1[u] = fmaf(0.5f, tanh_a(0.5f*g1), 0.5f);   // sigmoid: i / f
            a2[u] = fmaf(k1,   tanh_a(sc2*g2),  k0);     // tanh g / sigmoid o
        }
        #pragma unroll
        for (int u = 0; u < BPW; u++) {
            float fv = __shfl_sync(0xffffffffu, a1[u], lid + 10);
            float ov = __shfl_sync(0xffffffffu, a2[u], lid + 10);
            cc[u] = fmaf(fv, cc[u], a1[u]*a2[u]);
            float hv = ov * tanh_a(cc[u]);
            #pragma unroll
            for (int j = 0; j < H_SZ; j++)
                h[u][j] = __shfl_sync(0xffffffffu, hv, j);
            cur1[u] = n1[u]; cur2[u] = n2[u];
        }
    }

    if (lid < 2) {
        #pragma unroll
        for (int u = 0; u < BPW; u++) {
            float o = fcb[lid];
            #pragma unroll
            for (int j = 0; j < H_SZ; j++) o = fmaf(fcw[lid*H_SZ + j], h[u][j], o);
            out[(b0+u)*2 + lid] = o;
        }
    }
}

// ============================================================
extern "C" void kernel_launch(void* const* d_in, const int* in_sizes, int n_in,
                              void* d_out, int out_size)
{
    const float* x     = (const float*)d_in[0];
    const float* ctw   = (const float*)d_in[1];
    const float* ctb   = (const float*)d_in[2];
    const float* csw   = (const float*)d_in[3];
    const float* gamma = (const float*)d_in[4];
    const float* beta  = (const float*)d_in[5];
    const float* mean  = (const float*)d_in[6];
    const float* var   = (const float*)d_in[7];
    const float* wih   = (const float*)d_in[8];
    const float* whh   = (const float*)d_in[9];
    const float* bih   = (const float*)d_in[10];
    const float* bhh   = (const float*)d_in[11];
    const float* fcw   = (const float*)d_in[12];
    const float* fcb   = (const float*)d_in[13];
    float* out = (float*)d_out;

    cudaFuncSetAttribute(conv_kernel, cudaFuncAttributeMaxDynamicSharedMemorySize, CONV_SMEM_BYTES);
    cudaFuncSetAttribute(lstm_kernel, cudaFuncAttributeMaxDynamicSharedMemorySize, LSTM_SMEM_BYTES);

    prep_kernel<<<G_SZ, 256>>>(ctw, ctb, csw, gamma, beta, mean, var, wih, bih, bhh);
    conv_kernel<<<dim3(3, B_SZ), CONV_THREADS, CONV_SMEM_BYTES>>>(x);
    lstm_kernel<<<B_SZ/(LSTM_WARPS*BPW), 32*LSTM_WARPS, LSTM_SMEM_BYTES>>>(whh, fcw, fcb, out);
}

// round 10
// speedup vs baseline: 1.2967x; 1.2967x over previous
#include <cuda_runtime.h>
#include <math.h>
#include <cstdint>

// Problem dims
#define B_SZ 512
#define T_IN 1125
#define E_SZ 5
#define C_SZ 40
#define L_SZ 216
#define G_SZ 40
#define H_SZ 10
#define KK   125

// ---- persistent scratch ----
__device__ __align__(16) float d_Wcomb[KK*G_SZ];        // [kk][g]
__device__ __align__(16) float d_bg[G_SZ];
__device__ __align__(16) float d_xg[B_SZ*L_SZ*G_SZ];    // [b][t][g]

__device__ __forceinline__ float tanh_a(float x) {
    float r; asm("tanh.approx.f32 %0, %1;" : "=f"(r) : "f"(x)); return r;
}
__device__ __forceinline__ uint32_t smem_u32(const void* p) {
    uint32_t a;
    asm("{ .reg .u64 t; cvta.to.shared.u64 t, %1; cvt.u32.u64 %0, t; }" : "=r"(a) : "l"(p));
    return a;
}

// ============================================================
// Kernel 0: weight fold (R6-proven). 40 CTAs, one gate each.
// ============================================================
__global__ void __launch_bounds__(256) prep_kernel(
        const float* __restrict__ wt,     // [40][25]
        const float* __restrict__ tb,     // [40]
        const float* __restrict__ ws,     // [40][40][5]
        const float* __restrict__ gamma,
        const float* __restrict__ beta,
        const float* __restrict__ mean,
        const float* __restrict__ var,
        const float* __restrict__ wih,    // [40][40]
        const float* __restrict__ bih,
        const float* __restrict__ bhh)
{
    __shared__ __align__(16) float s_ws[C_SZ*C_SZ*E_SZ];   // 8000
    __shared__ __align__(16) float s_wt[C_SZ*25];
    __shared__ float s_wr[C_SZ], s_wsc[C_SZ], s_shift[C_SZ], s_tb[C_SZ];
    __shared__ float A_s[C_SZ*E_SZ];
    __shared__ float red[8];
    int t = threadIdx.x;
    int g = blockIdx.x;

    for (int i = t; i < 2000; i += 256) ((float4*)s_ws)[i] = ((const float4*)ws)[i];
    for (int i = t; i < 250;  i += 256) ((float4*)s_wt)[i] = ((const float4*)wt)[i];
    if (t < C_SZ) {
        float sc = gamma[t] * rsqrtf(var[t] + 1e-5f);
        float wr = wih[g*C_SZ + t];
        s_wr[t]  = wr;
        s_wsc[t] = wr * sc;
        s_shift[t] = beta[t] - mean[t]*sc;
        s_tb[t] = tb[t];
    }
    __syncthreads();

    if (t < C_SZ*E_SZ) {
        int cp = t / E_SZ, e = t % E_SZ;
        float s = 0.f;
        #pragma unroll 8
        for (int c = 0; c < C_SZ; c++) s += s_wsc[c] * s_ws[c*200 + cp*E_SZ + e];
        A_s[t] = s;
    }
    __syncthreads();

    if (t < KK) {
        int k = t / E_SZ, e = t % E_SZ;
        float s = 0.f;
        #pragma unroll 8
        for (int cp = 0; cp < C_SZ; cp++) s += A_s[cp*E_SZ + e] * s_wt[cp*25 + k];
        d_Wcomb[t*G_SZ + g] = s * (1.0f/25.0f);
    }

    float part = 0.f;
    for (int idx = t; idx < 1600; idx += 256) {
        int c = idx / C_SZ, cp = idx % C_SZ;
        const float* w5 = &s_ws[c*200 + cp*E_SZ];
        float s5 = w5[0]+w5[1]+w5[2]+w5[3]+w5[4];
        part += s_wsc[c] * s_tb[cp] * s5;
    }
    if (t < C_SZ) part += s_wr[t] * s_shift[t];
    #pragma unroll
    for (int o = 16; o > 0; o >>= 1) part += __shfl_xor_sync(0xffffffffu, part, o);
    if ((t & 31) == 0) red[t >> 5] = part;
    __syncthreads();
    if (t == 0) {
        float s = red[0]+red[1]+red[2]+red[3]+red[4]+red[5]+red[6]+red[7];
        d_bg[g] = bih[g] + bhh[g] + s;
    }
}

// ============================================================
// Kernel 1: conv/pool/GEMM — EXACT R6 structure (proven fastest):
// 3 tiles x 72p, 192 threads, early weight staging overlapped
// with x load, Bsum pass + transpose pass, 10x18 thread map.
// Only change vs R6: output stored in [b][t][g] layout.
// ============================================================
#define CONV_THREADS 192
#define PTILE 72
// smem floats
#define OFF_WS   0                 // 5000
#define OFF_BG   5000              // 40
#define OFF_BSUM 5040              // 1900 used (+4)
#define OFF_BST  6944              // 9000 = 125*72 (x slab 2020 aliased)
#define CONV_SMEM_FLOATS (6944 + 9000)          // 15944
#define CONV_SMEM_BYTES  (CONV_SMEM_FLOATS*4)   // 63776

__global__ void __launch_bounds__(CONV_THREADS) conv_kernel(const float* __restrict__ x)
{
    extern __shared__ float sm[];
    float* Ws   = sm + OFF_WS;
    float* bg_s = sm + OFF_BG;
    float* Bsum = sm + OFF_BSUM;
    float* Bst  = sm + OFF_BST;
    float* xs   = Bst;                 // alias: x slab dead before transpose

    int tid  = threadIdx.x;
    int q    = blockIdx.x;             // tile 0..2
    int b    = blockIdx.y;

    const float* xb = x + (size_t)b*(T_IN*E_SZ) + q*(PTILE*5*E_SZ);   // q*1800
    for (int i = tid; i < 2020; i += CONV_THREADS) xs[i] = xb[i];
    for (int i = tid; i < KK*G_SZ; i += CONV_THREADS) Ws[i] = d_Wcomb[i];
    if (tid < G_SZ) bg_s[tid] = d_bg[tid];
    __syncthreads();

    // Bsum[t*5+e] = sum_{j<25} xs[(t+j)*5+e], t in [0,380)
    {
        int e = tid % 5, seg = tid / 5;      // seg 0..38
        int t0 = seg*10;
        if (t0 < 380) {
            int t1 = min(t0+10, 380);
            float s = 0.f;
            #pragma unroll
            for (int j = 0; j < 25; j++) s += xs[(t0+j)*5 + e];
            Bsum[t0*5+e] = s;
            for (int tt = t0+1; tt < t1; tt++) {
                s += xs[(tt+24)*5+e] - xs[(tt-1)*5+e];
                Bsum[tt*5+e] = s;
            }
        }
    }
    __syncthreads();

    // transpose: Bst[kk*72 + pl] = Bsum[(5*pl + k)*5 + e],  kk = 5k+e
    for (int idx = tid; idx < KK*PTILE; idx += CONV_THREADS) {
        int kk = idx / PTILE;
        int pl = idx - kk*PTILE;
        int k  = kk / 5;
        int e  = kk - k*5;
        Bst[idx] = Bsum[(5*pl + k)*5 + e];
    }
    __syncthreads();

    if (tid < 180) {
        int gq = tid / 18;            // 0..9  -> gates 4gq..4gq+3
        int pq = tid - gq*18;         // 0..17 -> p 4pq..4pq+3
        const float4* wp = (const float4*)Ws  + gq;    // wp[kk*10]
        const float4* xq = (const float4*)Bst + pq;    // xq[kk*18]

        float4 bg4 = ((const float4*)bg_s)[gq];
        float a00=bg4.x,a01=bg4.x,a02=bg4.x,a03=bg4.x;
        float a10=bg4.y,a11=bg4.y,a12=bg4.y,a13=bg4.y;
        float a20=bg4.z,a21=bg4.z,a22=bg4.z,a23=bg4.z;
        float a30=bg4.w,a31=bg4.w,a32=bg4.w,a33=bg4.w;

        #pragma unroll 5
        for (int kk = 0; kk < KK; kk++) {
            float4 w  = wp[kk*10];
            float4 xv = xq[kk*18];
            a00 = fmaf(w.x, xv.x, a00); a01 = fmaf(w.x, xv.y, a01);
            a02 = fmaf(w.x, xv.z, a02); a03 = fmaf(w.x, xv.w, a03);
            a10 = fmaf(w.y, xv.x, a10); a11 = fmaf(w.y, xv.y, a11);
            a12 = fmaf(w.y, xv.z, a12); a13 = fmaf(w.y, xv.w, a13);
            a20 = fmaf(w.z, xv.x, a20); a21 = fmaf(w.z, xv.y, a21);
            a22 = fmaf(w.z, xv.z, a22); a23 = fmaf(w.z, xv.w, a23);
            a30 = fmaf(w.w, xv.x, a30); a31 = fmaf(w.w, xv.y, a31);
            a32 = fmaf(w.w, xv.z, a32); a33 = fmaf(w.w, xv.w, a33);
        }

        // xg layout [b][t][g]
        int p0 = q*PTILE + 4*pq;
        float* dst = d_xg + (size_t)b*(L_SZ*G_SZ) + p0*G_SZ + 4*gq;
        *(float4*)(dst         ) = make_float4(a00, a10, a20, a30);
        *(float4*)(dst +   G_SZ) = make_float4(a01, a11, a21, a31);
        *(float4*)(dst + 2*G_SZ) = make_float4(a02, a12, a22, a32);
        *(float4*)(dst + 3*G_SZ) = make_float4(a03, a13, a23, a33);
    }
}

// ============================================================
// Kernel 2: LSTM scan + FC. 2 batches per warp (ILP), contiguous
// xg slices staged via cp.async. (R8 verbatim — measured good)
// ============================================================
#define LSTM_WARPS 2
#define BPW 2
#define XSLICE_FLOATS (L_SZ*G_SZ)            // 8640
#define XSLICE_BYTES  (XSLICE_FLOATS*4)      // 34560
#define LSTM_SMEM_BYTES (LSTM_WARPS*BPW*XSLICE_BYTES + 256)

__global__ void __launch_bounds__(32*LSTM_WARPS) lstm_kernel(
        const float* __restrict__ whh,  // [40][10]
        const float* __restrict__ fcw,  // [2][10]
        const float* __restrict__ fcb,
        float* __restrict__ out)
{
    extern __shared__ float xsm[];
    int warp = threadIdx.x >> 5;
    int lid  = threadIdx.x & 31;
    int b0   = blockIdx.x*(LSTM_WARPS*BPW) + warp*BPW;

    {
        uint32_t dst0 = smem_u32(xsm) + warp*BPW*XSLICE_BYTES;
        #pragma unroll
        for (int u = 0; u < BPW; u++) {
            const char* src0 = (const char*)(d_xg + (size_t)(b0+u)*XSLICE_FLOATS);
            uint32_t d0 = dst0 + u*XSLICE_BYTES;
            for (int c = lid; c < 2160; c += 32) {
                asm volatile("cp.async.ca.shared.global [%0], [%1], 16;"
                             :: "r"(d0 + (uint32_t)(c*16)), "l"(src0 + (size_t)c*16));
            }
        }
        asm volatile("cp.async.commit_group;" ::: "memory");
        asm volatile("cp.async.wait_group 0;" ::: "memory");
        __syncwarp();
    }
    const float* xw[BPW];
    xw[0] = xsm + warp*BPW*XSLICE_FLOATS;
    xw[1] = xw[0] + XSLICE_FLOATS;

    int r = min(lid, 19);
    float wa[H_SZ], wb[H_SZ];
    #pragma unroll
    for (int j = 0; j < H_SZ; j++) {
        wa[j] = whh[r*H_SZ + j];
        wb[j] = whh[(r+20)*H_SZ + j];
    }
    const float sc2 = (lid < 10) ? 1.0f : 0.5f;
    const float k1  = (lid < 10) ? 1.0f : 0.5f;
    const float k0  = (lid < 10) ? 0.0f : 0.5f;

    float h[BPW][H_SZ], cc[BPW], cur1[BPW], cur2[BPW];
    #pragma unroll
    for (int u = 0; u < BPW; u++) {
        #pragma unroll
        for (int j = 0; j < H_SZ; j++) h[u][j] = 0.f;
        cc[u] = 0.f;
        cur1[u] = xw[u][r];
        cur2[u] = xw[u][20 + r];
    }

    for (int t = 0; t < L_SZ; t++) {
        float n1[BPW], n2[BPW];
        #pragma unroll
        for (int u = 0; u < BPW; u++) {           // overrun at t=215 lands in pad
            n1[u] = xw[u][(t+1)*G_SZ + r];
            n2[u] = xw[u][(t+1)*G_SZ + 20 + r];
        }
        float a1[BPW], a2[BPW];
        #pragma unroll
        for (int u = 0; u < BPW; u++) {
            float s1a = cur1[u], s1b = 0.f, s2a = cur2[u], s2b = 0.f;
            #pragma unroll
            for (int j = 0; j < 5; j++) {
                s1a = fmaf(wa[j],   h[u][j],   s1a);
                s1b = fmaf(wa[j+5], h[u][j+5], s1b);
                s2a = fmaf(wb[j],   h[u][j],   s2a);
                s2b = fmaf(wb[j+5], h[u][j+5], s2b);
            }
            float g1 = s1a + s1b;
            float g2 = s2a + s2b;
            a1[u] = fmaf(0.5f, tanh_a(0.5f*g1), 0.5f);   // sigmoid: i / f
            a2[u] = fmaf(k1,   tanh_a(sc2*g2),  k0);     // tanh g / sigmoid o
        }
        #pragma unroll
        for (int u = 0; u < BPW; u++) {
            float fv = __shfl_sync(0xffffffffu, a1[u], lid + 10);
            float ov = __shfl_sync(0xffffffffu, a2[u], lid + 10);
            cc[u] = fmaf(fv, cc[u], a1[u]*a2[u]);
            float hv = ov * tanh_a(cc[u]);
            #pragma unroll
            for (int j = 0; j < H_SZ; j++)
                h[u][j] = __shfl_sync(0xffffffffu, hv, j);
            cur1[u] = n1[u]; cur2[u] = n2[u];
        }
    }

    if (lid < 2) {
        #pragma unroll
        for (int u = 0; u < BPW; u++) {
            float o = fcb[lid];
            #pragma unroll
            for (int j = 0; j < H_SZ; j++) o = fmaf(fcw[lid*H_SZ + j], h[u][j], o);
            out[(b0+u)*2 + lid] = o;
        }
    }
}

// ============================================================
extern "C" void kernel_launch(void* const* d_in, const int* in_sizes, int n_in,
                              void* d_out, int out_size)
{
    const float* x     = (const float*)d_in[0];
    const float* ctw   = (const float*)d_in[1];
    const float* ctb   = (const float*)d_in[2];
    const float* csw   = (const float*)d_in[3];
    const float* gamma = (const float*)d_in[4];
    const float* beta  = (const float*)d_in[5];
    const float* mean  = (const float*)d_in[6];
    const float* var   = (const float*)d_in[7];
    const float* wih   = (const float*)d_in[8];
    const float* whh   = (const float*)d_in[9];
    const float* bih   = (const float*)d_in[10];
    const float* bhh   = (const float*)d_in[11];
    const float* fcw   = (const float*)d_in[12];
    const float* fcb   = (const float*)d_in[13];
    float* out = (float*)d_out;

    cudaFuncSetAttribute(conv_kernel, cudaFuncAttributeMaxDynamicSharedMemorySize, CONV_SMEM_BYTES);
    cudaFuncSetAttribute(lstm_kernel, cudaFuncAttributeMaxDynamicSharedMemorySize, LSTM_SMEM_BYTES);

    prep_kernel<<<G_SZ, 256>>>(ctw, ctb, csw, gamma, beta, mean, var, wih, bih, bhh);
    conv_kernel<<<dim3(3, B_SZ), CONV_THREADS, CONV_SMEM_BYTES>>>(x);
    lstm_kernel<<<B_SZ/(LSTM_WARPS*BPW), 32*LSTM_WARPS, LSTM_SMEM_BYTES>>>(whh, fcw, fcb, out);
}

// round 11
// speedup vs baseline: 1.4884x; 1.1478x over previous
#include <cuda_runtime.h>
#include <math.h>
#include <cstdint>

// Problem dims
#define B_SZ 512
#define T_IN 1125
#define E_SZ 5
#define C_SZ 40
#define L_SZ 216
#define G_SZ 40
#define H_SZ 10
#define KK   125

// ---- persistent scratch ----
__device__ __align__(16) float d_Wcomb[KK*G_SZ];        // [kk][g]
__device__ __align__(16) float d_bg[G_SZ];
__device__ __align__(16) float d_xg[B_SZ*L_SZ*G_SZ];    // [b][t][g]

__device__ __forceinline__ float tanh_a(float x) {
    float r; asm("tanh.approx.f32 %0, %1;" : "=f"(r) : "f"(x)); return r;
}
__device__ __forceinline__ uint32_t smem_u32(const void* p) {
    uint32_t a;
    asm("{ .reg .u64 t; cvta.to.shared.u64 t, %1; cvt.u32.u64 %0, t; }" : "=r"(a) : "l"(p));
    return a;
}

// ============================================================
// Kernel 0: weight fold (R6-proven). 40 CTAs, one gate each.
// ============================================================
__global__ void __launch_bounds__(256) prep_kernel(
        const float* __restrict__ wt,     // [40][25]
        const float* __restrict__ tb,     // [40]
        const float* __restrict__ ws,     // [40][40][5]
        const float* __restrict__ gamma,
        const float* __restrict__ beta,
        const float* __restrict__ mean,
        const float* __restrict__ var,
        const float* __restrict__ wih,    // [40][40]
        const float* __restrict__ bih,
        const float* __restrict__ bhh)
{
    __shared__ __align__(16) float s_ws[C_SZ*C_SZ*E_SZ];   // 8000
    __shared__ __align__(16) float s_wt[C_SZ*25];
    __shared__ float s_wr[C_SZ], s_wsc[C_SZ], s_shift[C_SZ], s_tb[C_SZ];
    __shared__ float A_s[C_SZ*E_SZ];
    __shared__ float red[8];
    int t = threadIdx.x;
    int g = blockIdx.x;

    for (int i = t; i < 2000; i += 256) ((float4*)s_ws)[i] = ((const float4*)ws)[i];
    for (int i = t; i < 250;  i += 256) ((float4*)s_wt)[i] = ((const float4*)wt)[i];
    if (t < C_SZ) {
        float sc = gamma[t] * rsqrtf(var[t] + 1e-5f);
        float wr = wih[g*C_SZ + t];
        s_wr[t]  = wr;
        s_wsc[t] = wr * sc;
        s_shift[t] = beta[t] - mean[t]*sc;
        s_tb[t] = tb[t];
    }
    __syncthreads();

    if (t < C_SZ*E_SZ) {
        int cp = t / E_SZ, e = t % E_SZ;
        float s = 0.f;
        #pragma unroll 8
        for (int c = 0; c < C_SZ; c++) s += s_wsc[c] * s_ws[c*200 + cp*E_SZ + e];
        A_s[t] = s;
    }
    __syncthreads();

    if (t < KK) {
        int k = t / E_SZ, e = t % E_SZ;
        float s = 0.f;
        #pragma unroll 8
        for (int cp = 0; cp < C_SZ; cp++) s += A_s[cp*E_SZ + e] * s_wt[cp*25 + k];
        d_Wcomb[t*G_SZ + g] = s * (1.0f/25.0f);
    }

    float part = 0.f;
    for (int idx = t; idx < 1600; idx += 256) {
        int c = idx / C_SZ, cp = idx % C_SZ;
        const float* w5 = &s_ws[c*200 + cp*E_SZ];
        float s5 = w5[0]+w5[1]+w5[2]+w5[3]+w5[4];
        part += s_wsc[c] * s_tb[cp] * s5;
    }
    if (t < C_SZ) part += s_wr[t] * s_shift[t];
    #pragma unroll
    for (int o = 16; o > 0; o >>= 1) part += __shfl_xor_sync(0xffffffffu, part, o);
    if ((t & 31) == 0) red[t >> 5] = part;
    __syncthreads();
    if (t == 0) {
        float s = red[0]+red[1]+red[2]+red[3]+red[4]+red[5]+red[6]+red[7];
        d_bg[g] = bih[g] + bhh[g] + s;
    }
}

// ============================================================
// Kernel 1: conv/pool/GEMM — R8's version VERBATIM (fastest
// measured conv): direct-transposed box sums, late weight
// staging, 192 threads, 56.2 KB smem, [b][t][g] output.
// ============================================================
#define CONV_THREADS 192
#define PTILE 72
#define OFF_WS   0
#define OFF_BG   5000
#define OFF_BST  5040              // 9000 = 125*72
#define CONV_SMEM_FLOATS (5040 + 9000)          // 14040
#define CONV_SMEM_BYTES  (CONV_SMEM_FLOATS*4)   // 56160

__global__ void __launch_bounds__(CONV_THREADS) conv_kernel(const float* __restrict__ x)
{
    extern __shared__ float sm[];
    float* xs   = sm;                  // phase 1-2 only
    float* Ws   = sm + OFF_WS;         // phase 3+ (overwrites xs)
    float* bg_s = sm + OFF_BG;
    float* Bst  = sm + OFF_BST;

    int tid = threadIdx.x;
    int q   = blockIdx.x;              // tile 0..2
    int b   = blockIdx.y;

    const float* xb = x + (size_t)b*(T_IN*E_SZ) + q*(PTILE*5*E_SZ);   // q*1800
    for (int i = tid; i < 2020; i += CONV_THREADS) xs[i] = xb[i];
    __syncthreads();

    // box sums written directly transposed:
    // for t in [0,380): s = sum_{j<25} xs[(t+j)*5+e]
    //   Bst[(5*(t%5) + 25*i + e)*72 + (t/5 - i)] = s for i=0..4, pl in range
    {
        int e = tid % 5, seg = tid / 5;      // seg 0..38 (seg 38 inactive)
        int t0 = seg*10;
        if (t0 < 380) {
            float s = 0.f;
            #pragma unroll
            for (int j = 0; j < 25; j++) s += xs[(t0+j)*5 + e];
            #pragma unroll 2
            for (int tt = t0; tt < t0+10; tt++) {
                if (tt > t0) s += xs[(tt+24)*5+e] - xs[(tt-1)*5+e];
                int qd = tt / 5, k0 = tt - 5*qd;
                int base = (5*k0 + e)*PTILE + qd;
                #pragma unroll
                for (int i = 0; i < 5; i++) {
                    int pl = qd - i;
                    if (pl >= 0 && pl < PTILE)
                        Bst[base + i*(25*PTILE) - i] = s;
                }
            }
        }
    }
    __syncthreads();

    // stage weights (xs dead)
    for (int i = tid; i < KK*G_SZ; i += CONV_THREADS) Ws[i] = d_Wcomb[i];
    if (tid < G_SZ) bg_s[tid] = d_bg[tid];
    __syncthreads();

    if (tid < 180) {
        int gq = tid / 18;            // 0..9  -> gates 4gq..4gq+3
        int pq = tid - gq*18;         // 0..17 -> p 4pq..4pq+3
        const float4* wp = (const float4*)Ws  + gq;    // wp[kk*10]
        const float4* xq = (const float4*)Bst + pq;    // xq[kk*18]

        float4 bg4 = ((const float4*)bg_s)[gq];
        float a00=bg4.x,a01=bg4.x,a02=bg4.x,a03=bg4.x;
        float a10=bg4.y,a11=bg4.y,a12=bg4.y,a13=bg4.y;
        float a20=bg4.z,a21=bg4.z,a22=bg4.z,a23=bg4.z;
        float a30=bg4.w,a31=bg4.w,a32=bg4.w,a33=bg4.w;

        #pragma unroll 5
        for (int kk = 0; kk < KK; kk++) {
            float4 w  = wp[kk*10];
            float4 xv = xq[kk*18];
            a00 = fmaf(w.x, xv.x, a00); a01 = fmaf(w.x, xv.y, a01);
            a02 = fmaf(w.x, xv.z, a02); a03 = fmaf(w.x, xv.w, a03);
            a10 = fmaf(w.y, xv.x, a10); a11 = fmaf(w.y, xv.y, a11);
            a12 = fmaf(w.y, xv.z, a12); a13 = fmaf(w.y, xv.w, a13);
            a20 = fmaf(w.z, xv.x, a20); a21 = fmaf(w.z, xv.y, a21);
            a22 = fmaf(w.z, xv.z, a22); a23 = fmaf(w.z, xv.w, a23);
            a30 = fmaf(w.w, xv.x, a30); a31 = fmaf(w.w, xv.y, a31);
            a32 = fmaf(w.w, xv.z, a32); a33 = fmaf(w.w, xv.w, a33);
        }

        // xg layout [b][t][g]
        int p0 = q*PTILE + 4*pq;
        float* dst = d_xg + (size_t)b*(L_SZ*G_SZ) + p0*G_SZ + 4*gq;
        *(float4*)(dst         ) = make_float4(a00, a10, a20, a30);
        *(float4*)(dst +   G_SZ) = make_float4(a01, a11, a21, a31);
        *(float4*)(dst + 2*G_SZ) = make_float4(a02, a12, a22, a32);
        *(float4*)(dst + 3*G_SZ) = make_float4(a03, a13, a23, a33);
    }
}

// ============================================================
// Kernel 2: LSTM scan + FC. NEW: lane l<10 owns ALL 4 gates of
// hidden unit l -> c and h are lane-local; the ONLY cross-lane
// op is the h-broadcast (one shfl stage per step, was three).
// 4 warps/CTA, 1 batch/warp, contiguous cp.async staging.
// ============================================================
#define LSTM_WARPS 4
#define XSLICE_FLOATS (L_SZ*G_SZ)            // 8640
#define XSLICE_BYTES  (XSLICE_FLOATS*4)      // 34560
#define LSTM_SMEM_BYTES (LSTM_WARPS*XSLICE_BYTES + 256)  // pad for t+1 overrun

__global__ void __launch_bounds__(32*LSTM_WARPS) lstm_kernel(
        const float* __restrict__ whh,  // [40][10]
        const float* __restrict__ fcw,  // [2][10]
        const float* __restrict__ fcb,
        float* __restrict__ out)
{
    extern __shared__ float xsm[];
    int warp = threadIdx.x >> 5;
    int lid  = threadIdx.x & 31;
    int b    = blockIdx.x*LSTM_WARPS + warp;

    // stage xg[b] (contiguous 34560 B) -> smem slice
    {
        uint32_t dst0 = smem_u32(xsm) + warp*XSLICE_BYTES;
        const char* src0 = (const char*)(d_xg + (size_t)b*XSLICE_FLOATS);
        for (int c = lid; c < 2160; c += 32) {
            asm volatile("cp.async.ca.shared.global [%0], [%1], 16;"
                         :: "r"(dst0 + (uint32_t)(c*16)), "l"(src0 + (size_t)c*16));
        }
        asm volatile("cp.async.commit_group;" ::: "memory");
        asm volatile("cp.async.wait_group 0;" ::: "memory");
        __syncwarp();
    }
    const float* xw = xsm + warp*XSLICE_FLOATS;

    int r = min(lid, 9);               // lanes >=10 mirror lane 9 (results unused)
    // per-lane gate weights: rows r (i), r+10 (f), r+20 (g), r+30 (o)
    float wi[H_SZ], wf[H_SZ], wg[H_SZ], wo[H_SZ];
    #pragma unroll
    for (int j = 0; j < H_SZ; j++) {
        wi[j] = whh[(r     )*H_SZ + j];
        wf[j] = whh[(r + 10)*H_SZ + j];
        wg[j] = whh[(r + 20)*H_SZ + j];
        wo[j] = whh[(r + 30)*H_SZ + j];
    }

    float h[H_SZ];
    #pragma unroll
    for (int j = 0; j < H_SZ; j++) h[j] = 0.f;
    float c = 0.f;

    float ci = xw[r], cf = xw[10+r], cg = xw[20+r], co = xw[30+r];
    for (int t = 0; t < L_SZ; t++) {
        // prefetch next step (t=215 overruns into pad)
        const float* nx = xw + (t+1)*G_SZ;
        float ni = nx[r], nf = nx[10+r], ng = nx[20+r], no = nx[30+r];

        // 8 independent 5-deep FMA chains (2 per gate)
        float ia = ci, ib = 0.f, fa = cf, fb = 0.f;
        float ga = cg, gb = 0.f, oa = co, ob = 0.f;
        #pragma unroll
        for (int j = 0; j < 5; j++) {
            ia = fmaf(wi[j], h[j], ia);  ib = fmaf(wi[j+5], h[j+5], ib);
            fa = fmaf(wf[j], h[j], fa);  fb = fmaf(wf[j+5], h[j+5], fb);
            ga = fmaf(wg[j], h[j], ga);  gb = fmaf(wg[j+5], h[j+5], gb);
            oa = fmaf(wo[j], h[j], oa);  ob = fmaf(wo[j+5], h[j+5], ob);
        }
        float iv = fmaf(0.5f, tanh_a(0.5f*(ia+ib)), 0.5f);   // sigmoid i
        float fv = fmaf(0.5f, tanh_a(0.5f*(fa+fb)), 0.5f);   // sigmoid f
        float gv = tanh_a(ga+gb);                            // tanh g
        float ov = fmaf(0.5f, tanh_a(0.5f*(oa+ob)), 0.5f);   // sigmoid o
        c = fmaf(fv, c, iv*gv);
        float hv = ov * tanh_a(c);
        #pragma unroll
        for (int j = 0; j < H_SZ; j++)
            h[j] = __shfl_sync(0xffffffffu, hv, j);
        ci = ni; cf = nf; cg = ng; co = no;
    }

    if (lid < 2) {
        float o = fcb[lid];
        #pragma unroll
        for (int j = 0; j < H_SZ; j++) o = fmaf(fcw[lid*H_SZ + j], h[j], o);
        out[b*2 + lid] = o;
    }
}

// ============================================================
extern "C" void kernel_launch(void* const* d_in, const int* in_sizes, int n_in,
                              void* d_out, int out_size)
{
    const float* x     = (const float*)d_in[0];
    const float* ctw   = (const float*)d_in[1];
    const float* ctb   = (const float*)d_in[2];
    const float* csw   = (const float*)d_in[3];
    const float* gamma = (const float*)d_in[4];
    const float* beta  = (const float*)d_in[5];
    const float* mean  = (const float*)d_in[6];
    const float* var   = (const float*)d_in[7];
    const float* wih   = (const float*)d_in[8];
    const float* whh   = (const float*)d_in[9];
    const float* bih   = (const float*)d_in[10];
    const float* bhh   = (const float*)d_in[11];
    const float* fcw   = (const float*)d_in[12];
    const float* fcb   = (const float*)d_in[13];
    float* out = (float*)d_out;

    cudaFuncSetAttribute(conv_kernel, cudaFuncAttributeMaxDynamicSharedMemorySize, CONV_SMEM_BYTES);
    cudaFuncSetAttribute(lstm_kernel, cudaFuncAttributeMaxDynamicSharedMemorySize, LSTM_SMEM_BYTES);

    prep_kernel<<<G_SZ, 256>>>(ctw, ctb, csw, gamma, beta, mean, var, wih, bih, bhh);
    conv_kernel<<<dim3(3, B_SZ), CONV_THREADS, CONV_SMEM_BYTES>>>(x);
    lstm_kernel<<<B_SZ/LSTM_WARPS, 32*LSTM_WARPS, LSTM_SMEM_BYTES>>>(whh, fcw, fcb, out);
}

// round 12
// speedup vs baseline: 1.9272x; 1.2948x over previous
#include <cuda_runtime.h>
#include <cuda_bf16.h>
#include <math.h>
#include <cstdint>

// Problem dims
#define B_SZ 512
#define T_IN 1125
#define E_SZ 5
#define C_SZ 40
#define L_SZ 216
#define G_SZ 40
#define H_SZ 10
#define KK   125

// ---- persistent scratch ----
__device__ __align__(16) float d_bg[G_SZ];
__device__ __align__(16) float d_xg[B_SZ*L_SZ*G_SZ];    // [b][t][g]
__device__ __align__(16) uint16_t d_Wbfhi[G_SZ*136];    // bf16 W[n][k], k padded to 136
__device__ __align__(16) uint16_t d_Wbflo[G_SZ*136];

__device__ __forceinline__ float tanh_a(float x) {
    float r; asm("tanh.approx.f32 %0, %1;" : "=f"(r) : "f"(x)); return r;
}
__device__ __forceinline__ uint32_t smem_u32(const void* p) {
    uint32_t a;
    asm("{ .reg .u64 t; cvta.to.shared.u64 t, %1; cvt.u32.u64 %0, t; }" : "=r"(a) : "l"(p));
    return a;
}
__device__ __forceinline__ void ldsm_x4(uint32_t* r, uint32_t addr) {
    asm volatile("ldmatrix.sync.aligned.m8n8.x4.shared.b16 {%0,%1,%2,%3}, [%4];"
        : "=r"(r[0]), "=r"(r[1]), "=r"(r[2]), "=r"(r[3]) : "r"(addr));
}
__device__ __forceinline__ void ldsm_x2(uint32_t* r, uint32_t addr) {
    asm volatile("ldmatrix.sync.aligned.m8n8.x2.shared.b16 {%0,%1}, [%2];"
        : "=r"(r[0]), "=r"(r[1]) : "r"(addr));
}
__device__ __forceinline__ void mma_bf16(float* d, const uint32_t* a, const uint32_t* b) {
    asm volatile("mma.sync.aligned.m16n8k16.row.col.f32.bf16.bf16.f32 "
        "{%0,%1,%2,%3}, {%4,%5,%6,%7}, {%8,%9}, {%0,%1,%2,%3};"
        : "+f"(d[0]), "+f"(d[1]), "+f"(d[2]), "+f"(d[3])
        : "r"(a[0]), "r"(a[1]), "r"(a[2]), "r"(a[3]), "r"(b[0]), "r"(b[1]));
}
__device__ __forceinline__ uint16_t bf16_rn(float v) {
    __nv_bfloat16 h = __float2bfloat16(v);
    return *reinterpret_cast<uint16_t*>(&h);
}

// ============================================================
// Kernel 0: weight fold -> bf16 hi/lo images [40][136] + bg[40].
// 40 CTAs, one gate each (R6-proven math).
// ============================================================
__global__ void __launch_bounds__(256) prep_kernel(
        const float* __restrict__ wt,     // [40][25]
        const float* __restrict__ tb,     // [40]
        const float* __restrict__ ws,     // [40][40][5]
        const float* __restrict__ gamma,
        const float* __restrict__ beta,
        const float* __restrict__ mean,
        const float* __restrict__ var,
        const float* __restrict__ wih,    // [40][40]
        const float* __restrict__ bih,
        const float* __restrict__ bhh)
{
    __shared__ __align__(16) float s_ws[C_SZ*C_SZ*E_SZ];   // 8000
    __shared__ __align__(16) float s_wt[C_SZ*25];
    __shared__ float s_wr[C_SZ], s_wsc[C_SZ], s_shift[C_SZ], s_tb[C_SZ];
    __shared__ float A_s[C_SZ*E_SZ];
    __shared__ float red[8];
    int t = threadIdx.x;
    int g = blockIdx.x;

    for (int i = t; i < 2000; i += 256) ((float4*)s_ws)[i] = ((const float4*)ws)[i];
    for (int i = t; i < 250;  i += 256) ((float4*)s_wt)[i] = ((const float4*)wt)[i];
    if (t < C_SZ) {
        float sc = gamma[t] * rsqrtf(var[t] + 1e-5f);
        float wr = wih[g*C_SZ + t];
        s_wr[t]  = wr;
        s_wsc[t] = wr * sc;
        s_shift[t] = beta[t] - mean[t]*sc;
        s_tb[t] = tb[t];
    }
    __syncthreads();

    if (t < C_SZ*E_SZ) {
        int cp = t / E_SZ, e = t % E_SZ;
        float s = 0.f;
        #pragma unroll 8
        for (int c = 0; c < C_SZ; c++) s += s_wsc[c] * s_ws[c*200 + cp*E_SZ + e];
        A_s[t] = s;
    }
    __syncthreads();

    if (t < KK) {
        int k = t / E_SZ, e = t % E_SZ;
        float s = 0.f;
        #pragma unroll 8
        for (int cp = 0; cp < C_SZ; cp++) s += A_s[cp*E_SZ + e] * s_wt[cp*25 + k];
        float w = s * (1.0f/25.0f);
        uint32_t bits = __float_as_uint(w);
        d_Wbfhi[g*136 + t] = (uint16_t)(bits >> 16);
        float lo = w - __uint_as_float(bits & 0xFFFF0000u);
        d_Wbflo[g*136 + t] = bf16_rn(lo);
    } else if (t < 136) {
        d_Wbfhi[g*136 + t] = 0;
        d_Wbflo[g*136 + t] = 0;
    }

    float part = 0.f;
    for (int idx = t; idx < 1600; idx += 256) {
        int c = idx / C_SZ, cp = idx % C_SZ;
        const float* w5 = &s_ws[c*200 + cp*E_SZ];
        float s5 = w5[0]+w5[1]+w5[2]+w5[3]+w5[4];
        part += s_wsc[c] * s_tb[cp] * s5;
    }
    if (t < C_SZ) part += s_wr[t] * s_shift[t];
    #pragma unroll
    for (int o = 16; o > 0; o >>= 1) part += __shfl_xor_sync(0xffffffffu, part, o);
    if ((t & 31) == 0) red[t >> 5] = part;
    __syncthreads();
    if (t == 0) {
        float s = red[0]+red[1]+red[2]+red[3]+red[4]+red[5]+red[6]+red[7];
        d_bg[g] = bih[g] + bhh[g] + s;
    }
}

// ============================================================
// Kernel 1: conv/pool/GEMM on TENSOR CORES (mma.sync bf16, 2-term
// hi/lo split: D = Ahi*Whi + Ahi*Wlo + Alo*Whi).
// CTA = (q half of 108 p, batch). 256 thr, 94KB smem, 2 CTAs/SM.
// ============================================================
#define CT 256
#define PHALF 108
// smem byte offsets
#define OB_WHI  0          // 10880
#define OB_WLO  10880      // -> 21760
#define OB_BG   21760      // 160 -> 21952 (pad)
#define OB_BSUM 21952      // 11200 -> 33152
#define OB_AHI  33152      // 112*136*2 = 30464 -> 63616
#define OB_ALO  63616      // 30464 -> 94080
#define OB_XS   63616      // x slab 11680 B, aliased into A_lo (dead before pack)
#define CONV_SMEM_BYTES 94080

__global__ void __launch_bounds__(CT) conv_kernel(const float* __restrict__ x)
{
    extern __shared__ char smc[];
    int tid  = threadIdx.x;
    int lane = tid & 31;
    int w    = tid >> 5;
    int q    = blockIdx.x;             // 0/1 -> p [0,108) / [108,216)
    int b    = blockIdx.y;

    // stage weights + bias + x slab (all overlapped)
    {
        const uint4* ghi = (const uint4*)d_Wbfhi;
        const uint4* glo = (const uint4*)d_Wbflo;
        uint4* shi = (uint4*)(smc + OB_WHI);
        uint4* slo = (uint4*)(smc + OB_WLO);
        for (int i = tid; i < 680; i += CT) { shi[i] = ghi[i]; slo[i] = glo[i]; }
    }
    if (tid < G_SZ) ((float*)(smc + OB_BG))[tid] = d_bg[tid];
    float* xs = (float*)(smc + OB_XS);
    {
        const float* xb = x + (size_t)b*(T_IN*E_SZ) + q*(PHALF*5*E_SZ);   // q*2700
        for (int i = tid; i < 2920; i += CT) xs[i] = xb[i];
    }
    __syncthreads();

    // box sums: Bsum[t*5+e] = sum_{j<25} xs[(t+j)*5+e], t in [0,560)
    float* Bsum = (float*)(smc + OB_BSUM);
    {
        int e = tid % 5, seg = tid / 5;      // seg 0..51
        int t0 = seg*11;
        if (t0 < 560) {
            int t1 = min(t0+11, 560);
            float s = 0.f;
            #pragma unroll
            for (int j = 0; j < 25; j++) s += xs[(t0+j)*5 + e];
            Bsum[t0*5+e] = s;
            for (int tt = t0+1; tt < t1; tt++) {
                s += xs[(tt+24)*5+e] - xs[(tt-1)*5+e];
                Bsum[tt*5+e] = s;
            }
        }
    }
    __syncthreads();

    // pack A: A[pl][kk] = Bsum[25*pl + kk] (kk<125), rows/cols padded 0.
    // hi = truncate-to-bf16, lo = rn-bf16(residual). (xs region now dead)
    {
        uint16_t* Ahi = (uint16_t*)(smc + OB_AHI);
        uint16_t* Alo = (uint16_t*)(smc + OB_ALO);
        for (int idx = tid; idx < 112*128; idx += CT) {
            int pl = idx >> 7;
            int kk = idx & 127;
            float val = (pl < PHALF && kk < KK) ? Bsum[25*pl + kk] : 0.f;
            uint32_t bits = __float_as_uint(val);
            Ahi[pl*136 + kk] = (uint16_t)(bits >> 16);
            float lo = val - __uint_as_float(bits & 0xFFFF0000u);
            Alo[pl*136 + kk] = bf16_rn(lo);
        }
    }
    __syncthreads();

    // MMA: 7 warps, warp w handles m-tile w (rows 16w..16w+15)
    if (w < 7) {
        uint32_t sbase = smem_u32(smc);
        // A addresses: lanes 0-15 -> rows 0-15 @ k0; lanes 16-31 -> rows @ k0+8
        uint32_t arow = (uint32_t)(16*w + (lane & 15));
        uint32_t acol = (uint32_t)((lane >> 4) * 8);
        uint32_t aoff = arow*272u + acol*2u;
        uint32_t ahi_addr = sbase + OB_AHI + aoff;
        uint32_t alo_addr = sbase + OB_ALO + aoff;
        // B addresses: bl = lane&15; rows n = nt*8 + (bl&7); k += (bl>=8)*8
        int bl = lane & 15;
        uint32_t brow = (uint32_t)(bl & 7);
        uint32_t bk8  = (uint32_t)(((bl >> 3) & 1) * 8);

        float D[5][4];
        #pragma unroll
        for (int nt = 0; nt < 5; nt++)
            #pragma unroll
            for (int j = 0; j < 4; j++) D[nt][j] = 0.f;

        #pragma unroll
        for (int ks = 0; ks < 8; ks++) {
            uint32_t ahi[4], alo[4];
            ldsm_x4(ahi, ahi_addr + ks*32u);
            ldsm_x4(alo, alo_addr + ks*32u);
            #pragma unroll
            for (int nt = 0; nt < 5; nt++) {
                uint32_t boff = ((uint32_t)(nt*8) + brow)*272u + ((uint32_t)(ks*16) + bk8)*2u;
                uint32_t bhi[2], blo[2];
                ldsm_x2(bhi, sbase + OB_WHI + boff);
                ldsm_x2(blo, sbase + OB_WLO + boff);
                mma_bf16(D[nt], ahi, bhi);
                mma_bf16(D[nt], ahi, blo);
                mma_bf16(D[nt], alo, bhi);
            }
        }

        // epilogue: add bias, store [b][t][g]
        const float* bgs = (const float*)(smc + OB_BG);
        int r0 = lane >> 2;
        int cp = (lane & 3) * 2;
        float* dst = d_xg + (size_t)b*(L_SZ*G_SZ) + (size_t)(q*PHALF)*G_SZ;
        int p_a = 16*w + r0;
        int p_b = p_a + 8;
        #pragma unroll
        for (int nt = 0; nt < 5; nt++) {
            int g = nt*8 + cp;
            float b0v = bgs[g], b1v = bgs[g+1];
            if (p_a < PHALF) {
                float2 v = make_float2(D[nt][0] + b0v, D[nt][1] + b1v);
                *(float2*)(dst + p_a*G_SZ + g) = v;
            }
            if (p_b < PHALF) {
                float2 v = make_float2(D[nt][2] + b0v, D[nt][3] + b1v);
                *(float2*)(dst + p_b*G_SZ + g) = v;
            }
        }
    }
}

// ============================================================
// Kernel 2: LSTM scan + FC (R11-proven: lane-local 4-gate units,
// one shfl stage per step, contiguous cp.async staging).
// ============================================================
#define LSTM_WARPS 4
#define XSLICE_FLOATS (L_SZ*G_SZ)            // 8640
#define XSLICE_BYTES  (XSLICE_FLOATS*4)      // 34560
#define LSTM_SMEM_BYTES (LSTM_WARPS*XSLICE_BYTES + 256)

__global__ void __launch_bounds__(32*LSTM_WARPS) lstm_kernel(
        const float* __restrict__ whh,  // [40][10]
        const float* __restrict__ fcw,  // [2][10]
        const float* __restrict__ fcb,
        float* __restrict__ out)
{
    extern __shared__ float xsm[];
    int warp = threadIdx.x >> 5;
    int lid  = threadIdx.x & 31;
    int b    = blockIdx.x*LSTM_WARPS + warp;

    {
        uint32_t dst0 = smem_u32(xsm) + warp*XSLICE_BYTES;
        const char* src0 = (const char*)(d_xg + (size_t)b*XSLICE_FLOATS);
        for (int c = lid; c < 2160; c += 32) {
            asm volatile("cp.async.ca.shared.global [%0], [%1], 16;"
                         :: "r"(dst0 + (uint32_t)(c*16)), "l"(src0 + (size_t)c*16));
        }
        asm volatile("cp.async.commit_group;" ::: "memory");
        asm volatile("cp.async.wait_group 0;" ::: "memory");
        __syncwarp();
    }
    const float* xw = xsm + warp*XSLICE_FLOATS;

    int r = min(lid, 9);
    float wi[H_SZ], wf[H_SZ], wg[H_SZ], wo[H_SZ];
    #pragma unroll
    for (int j = 0; j < H_SZ; j++) {
        wi[j] = whh[(r     )*H_SZ + j];
        wf[j] = whh[(r + 10)*H_SZ + j];
        wg[j] = whh[(r + 20)*H_SZ + j];
        wo[j] = whh[(r + 30)*H_SZ + j];
    }

    float h[H_SZ];
    #pragma unroll
    for (int j = 0; j < H_SZ; j++) h[j] = 0.f;
    float c = 0.f;

    float ci = xw[r], cf = xw[10+r], cg = xw[20+r], co = xw[30+r];
    for (int t = 0; t < L_SZ; t++) {
        const float* nx = xw + (t+1)*G_SZ;     // t=215 overruns into pad
        float ni = nx[r], nf = nx[10+r], ng = nx[20+r], no = nx[30+r];

        float ia = ci, ib = 0.f, fa = cf, fb = 0.f;
        float ga = cg, gb = 0.f, oa = co, ob = 0.f;
        #pragma unroll
        for (int j = 0; j < 5; j++) {
            ia = fmaf(wi[j], h[j], ia);  ib = fmaf(wi[j+5], h[j+5], ib);
            fa = fmaf(wf[j], h[j], fa);  fb = fmaf(wf[j+5], h[j+5], fb);
            ga = fmaf(wg[j], h[j], ga);  gb = fmaf(wg[j+5], h[j+5], gb);
            oa = fmaf(wo[j], h[j], oa);  ob = fmaf(wo[j+5], h[j+5], ob);
        }
        float iv = fmaf(0.5f, tanh_a(0.5f*(ia+ib)), 0.5f);
        float fv = fmaf(0.5f, tanh_a(0.5f*(fa+fb)), 0.5f);
        float gv = tanh_a(ga+gb);
        float ov = fmaf(0.5f, tanh_a(0.5f*(oa+ob)), 0.5f);
        c = fmaf(fv, c, iv*gv);
        float hv = ov * tanh_a(c);
        #pragma unroll
        for (int j = 0; j < H_SZ; j++)
            h[j] = __shfl_sync(0xffffffffu, hv, j);
        ci = ni; cf = nf; cg = ng; co = no;
    }

    if (lid < 2) {
        float o = fcb[lid];
        #pragma unroll
        for (int j = 0; j < H_SZ; j++) o = fmaf(fcw[lid*H_SZ + j], h[j], o);
        out[b*2 + lid] = o;
    }
}

// ============================================================
extern "C" void kernel_launch(void* const* d_in, const int* in_sizes, int n_in,
                              void* d_out, int out_size)
{
    const float* x     = (const float*)d_in[0];
    const float* ctw   = (const float*)d_in[1];
    const float* ctb   = (const float*)d_in[2];
    const float* csw   = (const float*)d_in[3];
    const float* gamma = (const float*)d_in[4];
    const float* beta  = (const float*)d_in[5];
    const float* mean  = (const float*)d_in[6];
    const float* var   = (const float*)d_in[7];
    const float* wih   = (const float*)d_in[8];
    const float* whh   = (const float*)d_in[9];
    const float* bih   = (const float*)d_in[10];
    const float* bhh   = (const float*)d_in[11];
    const float* fcw   = (const float*)d_in[12];
    const float* fcb   = (const float*)d_in[13];
    float* out = (float*)d_out;

    cudaFuncSetAttribute(conv_kernel, cudaFuncAttributeMaxDynamicSharedMemorySize, CONV_SMEM_BYTES);
    cudaFuncSetAttribute(lstm_kernel, cudaFuncAttributeMaxDynamicSharedMemorySize, LSTM_SMEM_BYTES);

    prep_kernel<<<G_SZ, 256>>>(ctw, ctb, csw, gamma, beta, mean, var, wih, bih, bhh);
    conv_kernel<<<dim3(2, B_SZ), CT, CONV_SMEM_BYTES>>>(x);
    lstm_kernel<<<B_SZ/LSTM_WARPS, 32*LSTM_WARPS, LSTM_SMEM_BYTES>>>(whh, fcw, fcb, out);
}